// round 1
// baseline (speedup 1.0000x reference)
#include <cuda_runtime.h>
#include <cstdint>
#include <math.h>

// ---------------------------------------------------------------------------
// SO3Reparameterize: z = expmap(x@Wmu+bmu) @ expmap(L @ (sqrt(softplus(x@Wd+bd))*eps))
// B=65536 rows, D_in=1024, n=1.  Fused single-pass kernel:
//   tall-skinny GEMM (N=9) with f32x2 packed FMAs + per-row SO(3) epilogue.
// Memory-bound: 256MB of x streamed once via cp.async smem staging.
// ---------------------------------------------------------------------------

#define B_ROWS   65536
#define D_IN     1024
#define NBLK     148
#define NTHR     224
#define ROWS_CAP 448                 // NTHR * 2 rows per thread
#define CHUNK_K  16                  // k floats per staged chunk
#define NCHUNK   (D_IN / CHUNK_K)    // 64
#define NPAIR    (CHUNK_K / 2)       // 8 k-pairs per chunk
#define ROW_F    18                  // staged floats per row (16 + 2 pad -> conflict-free LDS.64)
#define STAGES   4
#define SLOT_F   (ROWS_CAP * ROW_F)  // 8064 floats per stage
#define SLOT_B   (SLOT_F * 4)        // 32256 bytes
#define WP_U64   (512 * 10)          // 512 k-pairs x (9 coeffs + 1 pad) packed f32x2
#define WP_BYTES (WP_U64 * 8)        // 40960
#define SMEM_BYTES (WP_BYTES + STAGES * SLOT_B)  // 169984 <= 227KB

typedef unsigned long long ull;

__device__ __forceinline__ void fma2(ull &acc, ull x, ull w) {
    asm("fma.rn.f32x2 %0, %1, %2, %0;" : "+l"(acc) : "l"(x), "l"(w));
}
__device__ __forceinline__ ull pack2(float lo, float hi) {
    ull r; asm("mov.b64 %0, {%1, %2};" : "=l"(r) : "f"(lo), "f"(hi)); return r;
}
__device__ __forceinline__ float2 unpack2(ull v) {
    float2 f; asm("mov.b64 {%0, %1}, %2;" : "=f"(f.x), "=f"(f.y) : "l"(v)); return f;
}
__device__ __forceinline__ void cp8(uint32_t dst, const void* src) {
    asm volatile("cp.async.ca.shared.global [%0], [%1], 8;" :: "r"(dst), "l"(src) : "memory");
}
__device__ __forceinline__ void cp_commit() {
    asm volatile("cp.async.commit_group;" ::: "memory");
}
__device__ __forceinline__ void cp_wait2() {
    asm volatile("cp.async.wait_group 2;" ::: "memory");
}

__device__ __forceinline__ float softplus_f(float x) {
    // == logaddexp(x, 0)
    return fmaxf(x, 0.0f) + log1pf(expf(-fabsf(x)));
}

__device__ __forceinline__ void rodrigues(float vx, float vy, float vz, float R[9]) {
    float n2  = vx * vx + vy * vy + vz * vz;
    float th  = sqrtf(n2);
    float inv = 1.0f / th;                 // matches reference (no zero guard)
    float x = vx * inv, y = vy * inv, z = vz * inv;
    float s, c;
    sincosf(th, &s, &c);
    float C = 1.0f - c;
    float xC = x * C, yC = y * C, zC = z * C;
    float xs_ = x * s, ys_ = y * s, zs_ = z * s;
    R[0] = c + x * xC;  R[1] = x * yC - zs_; R[2] = x * zC + ys_;
    R[3] = x * yC + zs_; R[4] = c + y * yC;  R[5] = y * zC - xs_;
    R[6] = x * zC - ys_; R[7] = y * zC + xs_; R[8] = c + z * zC;
}

__device__ __forceinline__ void emit_row(const float y[9], int row,
                                         const float* __restrict__ eps,
                                         const float bm[3], const float bdv[3], const float blv[3],
                                         float* __restrict__ out)
{
    float mux = y[0] + bm[0], muy = y[1] + bm[1], muz = y[2] + bm[2];
    float d0 = softplus_f(y[3] + bdv[0]);
    float d1 = softplus_f(y[4] + bdv[1]);
    float d2 = softplus_f(y[5] + bdv[2]);
    float l0 = y[6] + blv[0], l1 = y[7] + blv[1], l2 = y[8] + blv[2];

    float e0 = __ldg(eps + (size_t)row * 3 + 0);
    float e1 = __ldg(eps + (size_t)row * 3 + 1);
    float e2 = __ldg(eps + (size_t)row * 3 + 2);

    float s0 = sqrtf(d0) * e0;
    float s1 = sqrtf(d1) * e1;
    float s2 = sqrtf(d2) * e2;

    // unit-lower-triangular L applied
    float v0 = s0;
    float v1 = l0 * s0 + s1;
    float v2 = l1 * s0 + l2 * s1 + s2;

    float Rm[9], Rv[9];
    rodrigues(mux, muy, muz, Rm);
    rodrigues(v0, v1, v2, Rv);

    float* o = out + (size_t)row * 9;
#pragma unroll
    for (int i = 0; i < 3; ++i) {
#pragma unroll
        for (int j = 0; j < 3; ++j) {
            o[i * 3 + j] = Rm[i * 3 + 0] * Rv[0 * 3 + j]
                         + Rm[i * 3 + 1] * Rv[1 * 3 + j]
                         + Rm[i * 3 + 2] * Rv[2 * 3 + j];
        }
    }
}

__global__ void __launch_bounds__(NTHR, 1)
so3_kernel(const float* __restrict__ x,   const float* __restrict__ eps,
           const float* __restrict__ Wmu, const float* __restrict__ bmu,
           const float* __restrict__ Wd,  const float* __restrict__ bd,
           const float* __restrict__ Wl,  const float* __restrict__ bl,
           float* __restrict__ out)
{
    extern __shared__ unsigned char smem[];
    ull*   Wp = (ull*)smem;                       // [512 k-pairs][10] f32x2 {W[2p][c], W[2p+1][c]}
    float* xs = (float*)(smem + WP_BYTES);        // [STAGES][ROWS_CAP][ROW_F]
    uint32_t xs_s = (uint32_t)__cvta_generic_to_shared(xs);

    const int t = threadIdx.x;
    const int b = blockIdx.x;
    const int start = (int)(((long long)b * B_ROWS) / NBLK);
    const int end   = (int)(((long long)(b + 1) * B_ROWS) / NBLK);
    const int nrows = end - start;                // 442 or 443 (<= 448)

    // ---- staging address precompute: thread covers 8B unit `pos` of rows r0+28j
    const int pos = t & 7;
    const int r0  = t >> 3;
    const float* sb[16];
    uint32_t so_[16];
#pragma unroll
    for (int j = 0; j < 16; ++j) {
        int r  = r0 + 28 * j;                     // 0..447
        int rg = start + r;
        if (rg > B_ROWS - 1) rg = B_ROWS - 1;     // clamp (duplicate reads are harmless)
        sb[j]  = x + (size_t)rg * D_IN + pos * 2;
        so_[j] = (uint32_t)((r * ROW_F + pos * 2) * 4);
    }

    // ---- prologue: launch chunks 0..STAGES-2
#pragma unroll
    for (int cpre = 0; cpre < STAGES - 1; ++cpre) {
        uint32_t base = xs_s + cpre * SLOT_B;
#pragma unroll
        for (int j = 0; j < 16; ++j) cp8(base + so_[j], sb[j] + cpre * CHUNK_K);
        cp_commit();
    }

    // ---- pack W into smem as k-pair f32x2 (overlapped with first TMA-less cp.asyncs)
    for (int i = t; i < WP_U64; i += NTHR) {
        int p = i / 10, c = i % 10;
        int k0 = 2 * p;
        float lo = 0.0f, hi = 0.0f;
        if (c < 3)      { lo = __ldg(Wmu + k0 * 3 + c);       hi = __ldg(Wmu + (k0 + 1) * 3 + c); }
        else if (c < 6) { lo = __ldg(Wd  + k0 * 3 + (c - 3)); hi = __ldg(Wd  + (k0 + 1) * 3 + (c - 3)); }
        else if (c < 9) { lo = __ldg(Wl  + k0 * 3 + (c - 6)); hi = __ldg(Wl  + (k0 + 1) * 3 + (c - 6)); }
        Wp[i] = pack2(lo, hi);
    }

    ull accA[9], accB[9];
#pragma unroll
    for (int c = 0; c < 9; ++c) { accA[c] = 0ull; accB[c] = 0ull; }

    const int ta = t, tb = t + NTHR;              // this thread's two staged rows

    // ---- main loop over 64 k-chunks, 4-stage cp.async ring, 1 sync per chunk
    for (int ch = 0; ch < NCHUNK; ++ch) {
        cp_wait2();                               // chunk `ch` landed (3 + ch groups committed)
        __syncthreads();                          // ...visible to all; all done reading ch-1

        const int slot = ch & (STAGES - 1);
        const float* pa = xs + slot * SLOT_F + ta * ROW_F;
        const float* pb = xs + slot * SLOT_F + tb * ROW_F;
        const ull* wrow = Wp + (size_t)ch * NPAIR * 10;

#pragma unroll
        for (int p = 0; p < NPAIR; ++p) {
            ull xa = *(const ull*)(pa + 2 * p);   // LDS.64, conflict-free (stride 9 mod 16)
            ull xb = *(const ull*)(pb + 2 * p);
            ulonglong2 w01 = *(const ulonglong2*)(wrow + p * 10 + 0);  // broadcast LDS.128
            ulonglong2 w23 = *(const ulonglong2*)(wrow + p * 10 + 2);
            ulonglong2 w45 = *(const ulonglong2*)(wrow + p * 10 + 4);
            ulonglong2 w67 = *(const ulonglong2*)(wrow + p * 10 + 6);
            ull        w8  = wrow[p * 10 + 8];
            fma2(accA[0], xa, w01.x); fma2(accB[0], xb, w01.x);
            fma2(accA[1], xa, w01.y); fma2(accB[1], xb, w01.y);
            fma2(accA[2], xa, w23.x); fma2(accB[2], xb, w23.x);
            fma2(accA[3], xa, w23.y); fma2(accB[3], xb, w23.y);
            fma2(accA[4], xa, w45.x); fma2(accB[4], xb, w45.x);
            fma2(accA[5], xa, w45.y); fma2(accB[5], xb, w45.y);
            fma2(accA[6], xa, w67.x); fma2(accB[6], xb, w67.x);
            fma2(accA[7], xa, w67.y); fma2(accB[7], xb, w67.y);
            fma2(accA[8], xa, w8);    fma2(accB[8], xb, w8);
        }

        // issue chunk ch+3 into slot (ch-1)&3 (safe: all warps passed this chunk's sync,
        // so everyone finished reading chunk ch-1). Always commit (empty groups keep
        // the wait_group arithmetic uniform).
        const int nc = ch + STAGES - 1;
        if (nc < NCHUNK) {
            uint32_t base = xs_s + (nc & (STAGES - 1)) * SLOT_B;
#pragma unroll
            for (int j = 0; j < 16; ++j) cp8(base + so_[j], sb[j] + nc * CHUNK_K);
        }
        cp_commit();
    }

    // ---- epilogue (pure registers, no further syncs)
    float bm[3], bdv[3], blv[3];
#pragma unroll
    for (int i = 0; i < 3; ++i) {
        bm[i]  = __ldg(bmu + i);
        bdv[i] = __ldg(bd + i);
        blv[i] = __ldg(bl + i);
    }

    {
        float y[9];
#pragma unroll
        for (int c = 0; c < 9; ++c) { float2 f = unpack2(accA[c]); y[c] = f.x + f.y; }
        emit_row(y, start + ta, eps, bm, bdv, blv, out);   // ta < 224 < nrows: always valid
    }
    if (tb < nrows) {
        float y[9];
#pragma unroll
        for (int c = 0; c < 9; ++c) { float2 f = unpack2(accB[c]); y[c] = f.x + f.y; }
        emit_row(y, start + tb, eps, bm, bdv, blv, out);
    }
}

extern "C" void kernel_launch(void* const* d_in, const int* in_sizes, int n_in,
                              void* d_out, int out_size)
{
    const float* x   = (const float*)d_in[0];
    const float* eps = (const float*)d_in[1];
    const float* Wmu = (const float*)d_in[2];
    const float* bmu = (const float*)d_in[3];
    const float* Wd  = (const float*)d_in[4];
    const float* bd  = (const float*)d_in[5];
    const float* Wl  = (const float*)d_in[6];
    const float* bl  = (const float*)d_in[7];

    cudaFuncSetAttribute(so3_kernel, cudaFuncAttributeMaxDynamicSharedMemorySize, SMEM_BYTES);
    so3_kernel<<<NBLK, NTHR, SMEM_BYTES>>>(x, eps, Wmu, bmu, Wd, bd, Wl, bl, (float*)d_out);
}